// round 1
// baseline (speedup 1.0000x reference)
#include <cuda_runtime.h>
#include <math.h>

// Problem constants (from reference)
#define BB   256
#define CC   16
#define TT   9000
#define KK   64      // crops per (b,c)
#define DT   300     // crop length
#define F0   7       // first kept rFFT bin (freq 0.7 Hz)
#define NF   35      // bins 7..41 inclusive
#define NTASK (KK * NF)   // 2240 tasks per (b,c)

__global__ __launch_bounds__(256, 1)
void st_sampling_goertzel(const float* __restrict__ inp,
                          const int*   __restrict__ offs,
                          float*       __restrict__ out)
{
    __shared__ float row[TT];          // 36000 B
    __shared__ float pow_s[NTASK];     //  8960 B
    __shared__ float inv_sum[KK];      //   256 B

    const int bc = blockIdx.x;                       // b*CC + c
    const float* src = inp + (size_t)bc * TT;

    // Stage the 9000-sample row into shared (coalesced float4: 9000/4 = 2250)
    for (int i = threadIdx.x; i < TT / 4; i += blockDim.x) {
        reinterpret_cast<float4*>(row)[i] =
            reinterpret_cast<const float4*>(src)[i];
    }
    __syncthreads();

    const int* o = offs + bc * KK;

    // Each task = one (crop k, bin f). Consecutive lanes share a crop ->
    // shared-row reads are warp broadcasts.
    for (int task = threadIdx.x; task < NTASK; task += blockDim.x) {
        const int k = task / NF;
        const int f = task - k * NF + F0;
        const int off = o[k];

        // Goertzel recurrence for integer bin f of a 300-pt DFT.
        const float w     = 6.283185307179586f * (float)f / (float)DT;
        const float coeff = 2.0f * cosf(w);

        const float* __restrict__ x = row + off;
        float s1 = 0.0f, s2 = 0.0f;
        #pragma unroll 10
        for (int t = 0; t < DT; ++t) {
            float s = fmaf(coeff, s1, x[t] - s2);
            s2 = s1;
            s1 = s;
        }
        // |X_f|^2 (forward-norm 1/N^2 and mean removal cancel in the
        // band normalization / don't affect bins 7..41)
        float p = fmaf(s1, s1, fmaf(s2, s2, -coeff * s1 * s2));
        pow_s[task] = p;
    }
    __syncthreads();

    // Per-crop band sum -> reciprocal
    if (threadIdx.x < KK) {
        const float* p = pow_s + threadIdx.x * NF;
        float s = 0.0f;
        #pragma unroll
        for (int f = 0; f < NF; ++f) s += p[f];
        inv_sum[threadIdx.x] = 1.0f / s;
    }
    __syncthreads();

    // Normalized write-out: out[b,c,k,f] contiguous
    float* ob = out + (size_t)bc * NTASK;
    for (int task = threadIdx.x; task < NTASK; task += blockDim.x) {
        ob[task] = pow_s[task] * inv_sum[task / NF];
    }
}

extern "C" void kernel_launch(void* const* d_in, const int* in_sizes, int n_in,
                              void* d_out, int out_size)
{
    const float* inp  = (const float*)d_in[0];   // [B, C, T] float32
    const int*   offs = (const int*)  d_in[1];   // [B, C, K] int32
    float*       out  = (float*)d_out;           // [B, C, K, NF] float32

    (void)in_sizes; (void)n_in; (void)out_size;

    dim3 grid(BB * CC);   // 4096 blocks, one per (b,c) row
    dim3 block(256);
    st_sampling_goertzel<<<grid, block>>>(inp, offs, out);
}

// round 7
// speedup vs baseline: 1.2006x; 1.2006x over previous
#include <cuda_runtime.h>

// Problem constants
#define BB   256
#define CC   16
#define TT   9000
#define KK   64      // crops per (b,c)
#define DT   300     // crop length
#define F0   7       // first kept rFFT bin
#define NF   35      // bins 7..41 inclusive
#define NCROP (BB * CC * KK)   // 262144 crops

// ---- compile-time cos via Taylor (|x| <= 0.86, remainder ~4e-15) ----
__host__ __device__ constexpr double ccos(double x) {
    double x2 = x * x;
    return 1.0 - x2/2.0*(1.0 - x2/12.0*(1.0 - x2/30.0*(1.0 - x2/56.0*
           (1.0 - x2/90.0*(1.0 - x2/132.0*(1.0 - x2/182.0))))));
}
__host__ __device__ constexpr float CF(int f) {
    // 2*cos(2*pi*f/300)
    return (float)(2.0 * ccos(0.020943951023931953 * (double)f));
}

__global__ __launch_bounds__(256)
void st_goertzel35(const float* __restrict__ inp,
                   const int*   __restrict__ offs,
                   float*       __restrict__ out)
{
    // Goertzel coefficients as compile-time literals -> FFMA-imm in SASS
    constexpr float COEF[NF] = {
        CF(7),  CF(8),  CF(9),  CF(10), CF(11), CF(12), CF(13),
        CF(14), CF(15), CF(16), CF(17), CF(18), CF(19), CF(20),
        CF(21), CF(22), CF(23), CF(24), CF(25), CF(26), CF(27),
        CF(28), CF(29), CF(30), CF(31), CF(32), CF(33), CF(34),
        CF(35), CF(36), CF(37), CF(38), CF(39), CF(40), CF(41)
    };

    const int tid = blockIdx.x * blockDim.x + threadIdx.x;   // crop id
    // k = tid & 63 fastest -> a warp covers 32 crops of the SAME input row
    const int bc  = tid >> 6;

    const int off = offs[tid];                               // [B,C,K] linear == tid
    const float* __restrict__ x = inp + (size_t)bc * TT + off;

    float s1[NF], s2[NF];
    #pragma unroll
    for (int j = 0; j < NF; ++j) { s1[j] = 0.0f; s2[j] = 0.0f; }

    // Goertzel over the 300-sample crop: one load feeds 70 FMAs.
    // Mean removal is a no-op for bins >= 1; forward-norm cancels in the
    // band normalization.
    #pragma unroll 4
    for (int t = 0; t < DT; ++t) {
        const float xv = __ldg(x + t);
        #pragma unroll
        for (int j = 0; j < NF; ++j) {
            float u = fmaf(s2[j], -1.0f, xv);       // x - s2  (imm -1.0)
            float s = fmaf(COEF[j], s1[j], u);      // + coeff*s1 (imm coeff)
            s2[j] = s1[j];
            s1[j] = s;
        }
    }

    // |X_f|^2 = s1^2 + s2^2 - coeff*s1*s2 ; then normalize band to unit sum
    float p[NF];
    float sum = 0.0f;
    #pragma unroll
    for (int j = 0; j < NF; ++j) {
        float v = fmaf(s1[j], s1[j],
                  fmaf(s2[j], s2[j], -COEF[j] * s1[j] * s2[j]));
        p[j] = v;
        sum += v;
    }
    const float inv = 1.0f / sum;

    float* __restrict__ o = out + (size_t)tid * NF;
    #pragma unroll
    for (int j = 0; j < NF; ++j) o[j] = p[j] * inv;
}

extern "C" void kernel_launch(void* const* d_in, const int* in_sizes, int n_in,
                              void* d_out, int out_size)
{
    const float* inp  = (const float*)d_in[0];   // [B, C, T] float32
    const int*   offs = (const int*)  d_in[1];   // [B, C, K] int32
    float*       out  = (float*)d_out;           // [B, C, K, NF] float32

    (void)in_sizes; (void)n_in; (void)out_size;

    st_goertzel35<<<NCROP / 256, 256>>>(inp, offs, out);
}

// round 10
// speedup vs baseline: 1.2067x; 1.0052x over previous
#include <cuda_runtime.h>

// Problem constants
#define BB   256
#define CC   16
#define TT   9000
#define KK   64      // crops per (b,c)
#define DT   300     // crop length
#define F0   7       // first kept rFFT bin
#define NF   35      // bins 7..41 inclusive
#define NP   18      // bin pairs (last one padded with dummy bin 42)
#define NCROP (BB * CC * KK)   // 262144 crops

typedef unsigned long long u64;

// ---- compile-time cos via Taylor (|x| <= 0.90, remainder ~1e-14) ----
__host__ __device__ constexpr double ccos(double x) {
    double x2 = x * x;
    return 1.0 - x2/2.0*(1.0 - x2/12.0*(1.0 - x2/30.0*(1.0 - x2/56.0*
           (1.0 - x2/90.0*(1.0 - x2/132.0*(1.0 - x2/182.0))))));
}
__host__ __device__ constexpr float CF(int f) {
    // 2*cos(2*pi*f/300)
    return (float)(2.0 * ccos(0.020943951023931953 * (double)f));
}

// ---- packed f32x2 helpers (sm_100+: FFMA2 only reachable via PTX) ----
__device__ __forceinline__ u64 pk2(float lo, float hi) {
    u64 r;
    asm("mov.b64 %0, {%1, %2};" : "=l"(r) : "f"(lo), "f"(hi));
    return r;
}
__device__ __forceinline__ void unpk2(float& lo, float& hi, u64 v) {
    asm("mov.b64 {%0, %1}, %2;" : "=f"(lo), "=f"(hi) : "l"(v));
}
__device__ __forceinline__ u64 fma2(u64 a, u64 b, u64 c) {
    u64 d;
    asm("fma.rn.f32x2 %0, %1, %2, %3;" : "=l"(d) : "l"(a), "l"(b), "l"(c));
    return d;
}

__global__ __launch_bounds__(256)
void st_goertzel_f32x2(const float* __restrict__ inp,
                       const int*   __restrict__ offs,
                       float*       __restrict__ out)
{
    const int tid = blockIdx.x * blockDim.x + threadIdx.x;   // crop id
    const int bc  = tid >> 6;        // warp covers 32 crops of the SAME row

    const int off = offs[tid];       // [B,C,K] linear == tid
    const float* __restrict__ x = inp + (size_t)bc * TT + off;

    // Packed Goertzel coefficient pairs (bins F0+2p, F0+2p+1); bin 42 = pad.
    u64 CP[NP];
    #pragma unroll
    for (int p = 0; p < NP; ++p)
        CP[p] = pk2(CF(F0 + 2*p), CF(F0 + 2*p + 1));

    const u64 NEG1 = pk2(-1.0f, -1.0f);

    u64 S1[NP], S2[NP];
    #pragma unroll
    for (int p = 0; p < NP; ++p) { S1[p] = 0ULL; S2[p] = 0ULL; }

    // Goertzel recurrence, 2 bins per FFMA2. Mean removal is a no-op for
    // bins >= 1; the forward-norm 1/N cancels in the band normalization.
    #pragma unroll 2
    for (int t = 0; t < DT; ++t) {
        const float xv = __ldg(x + t);
        const u64 X = pk2(xv, xv);
        #pragma unroll
        for (int p = 0; p < NP; ++p) {
            u64 u = fma2(S2[p], NEG1, X);       // (x - s2) in both lanes
            u64 s = fma2(CP[p], S1[p], u);      // + coeff*s1
            S2[p] = S1[p];
            S1[p] = s;
        }
    }

    // |X_f|^2 = s1^2 + s2^2 - coeff*s1*s2 ; then normalize band to unit sum
    float pw[NF];
    float sum = 0.0f;
    #pragma unroll
    for (int p = 0; p < NP; ++p) {
        float a1, b1, a2, b2, cl, ch;
        unpk2(a1, b1, S1[p]);
        unpk2(a2, b2, S2[p]);
        unpk2(cl, ch, CP[p]);
        int j = 2 * p;
        float v0 = fmaf(a1, a1, fmaf(a2, a2, -cl * a1 * a2));
        pw[j] = v0;  sum += v0;
        if (j + 1 < NF) {
            float v1 = fmaf(b1, b1, fmaf(b2, b2, -ch * b1 * b2));
            pw[j + 1] = v1;  sum += v1;
        }
    }
    const float inv = 1.0f / sum;

    float* __restrict__ o = out + (size_t)tid * NF;
    #pragma unroll
    for (int j = 0; j < NF; ++j) o[j] = pw[j] * inv;
}

extern "C" void kernel_launch(void* const* d_in, const int* in_sizes, int n_in,
                              void* d_out, int out_size)
{
    const float* inp  = (const float*)d_in[0];   // [B, C, T] float32
    const int*   offs = (const int*)  d_in[1];   // [B, C, K] int32
    float*       out  = (float*)d_out;           // [B, C, K, NF] float32

    (void)in_sizes; (void)n_in; (void)out_size;

    st_goertzel_f32x2<<<NCROP / 256, 256>>>(inp, offs, out);
}

// round 12
// speedup vs baseline: 1.5360x; 1.2729x over previous
#include <cuda_runtime.h>
#include <cuda_bf16.h>
#include <math.h>
#include <stdint.h>

// ---------------- problem constants ----------------
#define BB 256
#define CC 16
#define TT 9000
#define KK 64
#define DT 300
#define F0 7
#define NF 35
#define NCROP (BB*CC*KK)      // 262144

// ---------------- tile constants ----------------
#define M_TILE   128          // crops per CTA (8 warps x 16)
#define N_TILE   72           // 35 Re/Im pairs + 2 pad cols
#define NTILES   9            // 72 / 8
#define NCHUNK   5            // K = 5 * 64 (logical 300, rest zero)
#define ROWPITCH 144          // bytes per A row in SMEM (64 bf16 + pad)

// B fragments: [chunk][kstep 4][ntile 9][lane 32] x uint4{bhi0,bhi1,blo0,blo1}
#define BFRAG_CHUNK (4*NTILES*32*16)        // 18432 B
#define BFRAG_BYTES (NCHUNK*BFRAG_CHUNK)    // 92160 B

// ---------------- dynamic SMEM layout ----------------
#define SM_PTR  0                       // 128 crop pointers (8 B)
#define SM_AHI  1024
#define SM_ALO  (SM_AHI + M_TILE*ROWPITCH)   // 19456
#define SM_BF   (SM_ALO + M_TILE*ROWPITCH)   // 37888
#define SM_POW  SM_AHI                       // epilogue staging (17920 B)
#define SM_TOTAL (SM_BF + BFRAG_CHUNK)       // 56320

__device__ __align__(16) unsigned char g_Bfrag[BFRAG_BYTES];

// ---------------- helpers ----------------
__device__ __forceinline__ uint32_t smem_u32(const void* p) {
    uint32_t a;
    asm("{ .reg .u64 t; cvta.to.shared.u64 t, %1; cvt.u32.u64 %0, t; }"
        : "=r"(a) : "l"(p));
    return a;
}
__device__ __forceinline__ void ldmatrix4(uint32_t& r0, uint32_t& r1,
                                          uint32_t& r2, uint32_t& r3,
                                          uint32_t addr) {
    asm volatile("ldmatrix.sync.aligned.m8n8.x4.shared.b16 {%0,%1,%2,%3}, [%4];"
                 : "=r"(r0), "=r"(r1), "=r"(r2), "=r"(r3) : "r"(addr));
}
__device__ __forceinline__ void mma16816(float* c, uint32_t a0, uint32_t a1,
                                         uint32_t a2, uint32_t a3,
                                         uint32_t b0, uint32_t b1) {
    asm volatile(
        "mma.sync.aligned.m16n8k16.row.col.f32.bf16.bf16.f32 "
        "{%0,%1,%2,%3}, {%4,%5,%6,%7}, {%8,%9}, {%0,%1,%2,%3};"
        : "+f"(c[0]), "+f"(c[1]), "+f"(c[2]), "+f"(c[3])
        : "r"(a0), "r"(a1), "r"(a2), "r"(a3), "r"(b0), "r"(b1));
}

// W value at (phys index p within chunk c, output col m)
__device__ float wval(int c, int p, int m) {
    int l = p >> 1;
    int k = 64 * c + l + ((p & 1) ? 32 : 0);   // K permutation
    if (k >= DT || m >= 2 * NF) return 0.0f;
    int f = F0 + (m >> 1);
    double ang = 6.283185307179586476925286766559 * (double)f * (double)k / (double)DT;
    return (float)((m & 1) ? sin(ang) : cos(ang));
}

__global__ void build_Bfrag() {
    int t = blockIdx.x * blockDim.x + threadIdx.x;
    if (t >= NCHUNK * 4 * NTILES * 32) return;
    int lane = t & 31;
    int n = (t >> 5) % NTILES;
    int s = (t >> 5) / NTILES % 4;
    int c = t / (32 * NTILES * 4);

    int q = lane & 3, d = lane >> 2;
    int m  = 8 * n + d;
    int p0 = 16 * s + 2 * q;       // phys rows for b0: p0, p0+1 ; b1: p0+8, p0+9

    float w[4];
    w[0] = wval(c, p0,     m);
    w[1] = wval(c, p0 + 1, m);
    w[2] = wval(c, p0 + 8, m);
    w[3] = wval(c, p0 + 9, m);

    uint32_t h[4], lo[4];
    #pragma unroll
    for (int i = 0; i < 4; ++i) {
        __nv_bfloat16 hb = __float2bfloat16(w[i]);
        __nv_bfloat16 lb = __float2bfloat16(w[i] - __bfloat162float(hb));
        h[i]  = (uint32_t)__bfloat16_as_ushort(hb);
        lo[i] = (uint32_t)__bfloat16_as_ushort(lb);
    }
    uint4 v;
    v.x = h[0]  | (h[1]  << 16);   // bhi0
    v.y = h[2]  | (h[3]  << 16);   // bhi1
    v.z = lo[0] | (lo[1] << 16);   // blo0
    v.w = lo[2] | (lo[3] << 16);   // blo1
    ((uint4*)g_Bfrag)[((c * 4 + s) * NTILES + n) * 32 + lane] = v;
}

__global__ __launch_bounds__(256)
void st_dft_hmma(const float* __restrict__ inp,
                 const int*   __restrict__ offs,
                 float*       __restrict__ out)
{
    extern __shared__ __align__(16) unsigned char smem[];
    const uint32_t sbase = smem_u32(smem);
    const int tid  = threadIdx.x;
    const int wid  = tid >> 5;
    const int lane = tid & 31;
    const int base = blockIdx.x * M_TILE;

    if (tid < M_TILE) {
        int crop = base + tid;
        *(const float**)(smem + SM_PTR + tid * 8) =
            inp + (size_t)(crop >> 6) * TT + offs[crop];
    }

    float acc[NTILES * 4];
    #pragma unroll
    for (int i = 0; i < NTILES * 4; ++i) acc[i] = 0.0f;

    // ldmatrix row address for this lane (A fragment standard mapping)
    const uint32_t arow = sbase + SM_AHI
                        + (uint32_t)((16 * wid + (lane & 15)) * ROWPITCH)
                        + (uint32_t)(((lane >> 4) & 1) << 4);

    for (int c = 0; c < NCHUNK; ++c) {
        __syncthreads();   // previous iteration's reads complete

        // --- stage B fragments for this chunk (18432 B) ---
        {
            const uint4* src = (const uint4*)(g_Bfrag + c * BFRAG_CHUNK);
            uint4* dst = (uint4*)(smem + SM_BF);
            #pragma unroll
            for (int i = tid; i < BFRAG_CHUNK / 16; i += 256) dst[i] = src[i];
        }
        // --- gather A chunk: warp per row, coalesced, K-permuted bf16x2 ---
        for (int r = wid; r < M_TILE; r += 8) {
            const float* p = *(const float* const*)(smem + SM_PTR + r * 8);
            float x1 = __ldg(p + 64 * c + lane);           // k <= 287, always valid
            float x2 = 0.0f;
            if (c < 4 || lane < 12)                        // k = 64c+32+lane < 300
                x2 = __ldg(p + 64 * c + 32 + lane);
            uint32_t hp, lp;
            asm("cvt.rn.bf16x2.f32 %0, %1, %2;" : "=r"(hp) : "f"(x2), "f"(x1));
            float h1 = __uint_as_float(hp << 16);
            float h2 = __uint_as_float(hp & 0xffff0000u);
            float l1 = x1 - h1, l2 = x2 - h2;
            asm("cvt.rn.bf16x2.f32 %0, %1, %2;" : "=r"(lp) : "f"(l2), "f"(l1));
            unsigned o = (unsigned)(r * ROWPITCH + lane * 4);
            *(uint32_t*)(smem + SM_AHI + o) = hp;
            *(uint32_t*)(smem + SM_ALO + o) = lp;
        }
        __syncthreads();

        // --- 4 k-steps x 9 n-tiles x 3 split products ---
        #pragma unroll
        for (int s = 0; s < 4; ++s) {
            uint32_t ah0, ah1, ah2, ah3, al0, al1, al2, al3;
            ldmatrix4(ah0, ah1, ah2, ah3, arow + 32 * s);
            ldmatrix4(al0, al1, al2, al3, arow + (SM_ALO - SM_AHI) + 32 * s);
            #pragma unroll
            for (int n = 0; n < NTILES; ++n) {
                uint4 b = *(const uint4*)(smem + SM_BF
                          + (((s * NTILES + n) * 32 + lane) << 4));
                mma16816(acc + n * 4, ah0, ah1, ah2, ah3, b.x, b.y);  // AhiBhi
                mma16816(acc + n * 4, ah0, ah1, ah2, ah3, b.z, b.w);  // AhiBlo
                mma16816(acc + n * 4, al0, al1, al2, al3, b.x, b.y);  // AloBhi
            }
        }
    }
    __syncthreads();   // all mma reads done before reusing A buffer

    // --- epilogue: power, band-normalize, stage, coalesced store ---
    // C frag: c0=C[la/4][8n+2q], c1=+1 col, c2/c3 = rows +8.
    {
        const int q = lane & 3;
        const int rA = 16 * wid + (lane >> 2);
        const int rB = rA + 8;

        float pA[NTILES], pB[NTILES];
        float sA = 0.0f, sB = 0.0f;
        #pragma unroll
        for (int n = 0; n < NTILES; ++n) {
            pA[n] = fmaf(acc[n*4+0], acc[n*4+0], acc[n*4+1] * acc[n*4+1]);
            pB[n] = fmaf(acc[n*4+2], acc[n*4+2], acc[n*4+3] * acc[n*4+3]);
            sA += pA[n];  sB += pB[n];   // pad col j=35 contributes exactly 0
        }
        sA += __shfl_xor_sync(0xffffffffu, sA, 1);
        sA += __shfl_xor_sync(0xffffffffu, sA, 2);
        sB += __shfl_xor_sync(0xffffffffu, sB, 1);
        sB += __shfl_xor_sync(0xffffffffu, sB, 2);
        const float iA = 1.0f / sA, iB = 1.0f / sB;

        float* pw = (float*)(smem + SM_POW);
        #pragma unroll
        for (int n = 0; n < NTILES; ++n) {
            int j = 4 * n + q;
            if (j < NF) {
                pw[rA * NF + j] = pA[n] * iA;
                pw[rB * NF + j] = pB[n] * iB;
            }
        }
    }
    __syncthreads();

    {
        uint4* o = (uint4*)(out + (size_t)base * NF);
        const uint4* s = (const uint4*)(smem + SM_POW);
        #pragma unroll
        for (int i = tid; i < (M_TILE * NF * 4) / 16; i += 256) o[i] = s[i];
    }
}

extern "C" void kernel_launch(void* const* d_in, const int* in_sizes, int n_in,
                              void* d_out, int out_size)
{
    const float* inp  = (const float*)d_in[0];   // [B, C, T] float32
    const int*   offs = (const int*)  d_in[1];   // [B, C, K] int32
    float*       out  = (float*)d_out;           // [B, C, K, NF] float32

    (void)in_sizes; (void)n_in; (void)out_size;

    static int configured = 0;
    if (!configured) {
        cudaFuncSetAttribute(st_dft_hmma,
                             cudaFuncAttributeMaxDynamicSharedMemorySize, SM_TOTAL);
        configured = 1;
    }

    build_Bfrag<<<(NCHUNK * 4 * NTILES * 32 + 255) / 256, 256>>>();
    st_dft_hmma<<<NCROP / M_TILE, 256, SM_TOTAL>>>(inp, offs, out);
}

// round 13
// speedup vs baseline: 2.1832x; 1.4213x over previous
#include <cuda_runtime.h>
#include <cuda_bf16.h>
#include <math.h>
#include <stdint.h>

// ---------------- problem constants ----------------
#define BB 256
#define CC 16
#define TT 9000
#define KK 64
#define DT 300
#define F0 7
#define NF 35
#define NCROP (BB*CC*KK)      // 262144

// ---------------- tile constants ----------------
#define M_TILE   128          // crops per CTA (8 warps x 16 rows)
#define NTILES   9            // 72 cols / 8
#define NCHUNK   5            // K = 5 * 64 (logical 300, rest zero)
#define ROWPITCH 144          // bytes per A row in SMEM (64 bf16 + 16 pad)
#define A_HALF   (M_TILE*ROWPITCH)       // 18432 (one hi or lo plane)

// B fragments: [chunk][kstep 4][ntile 9][lane 32] x uint4{bhi0,bhi1,blo0,blo1}
#define BFRAG_CHUNK (4*NTILES*32*16)     // 18432 B
#define BFRAG_BYTES (NCHUNK*BFRAG_CHUNK) // 92160 B

// ---------------- dynamic SMEM layout ----------------
#define SM_PTR  0                        // 128 crop pointers (8 B each)
#define SM_A0   1024                     // buf0: hi @ +0, lo @ +A_HALF
#define SM_A1   (SM_A0 + 2*A_HALF)       // 37888
#define SM_B0   (SM_A1 + 2*A_HALF)       // 74752
#define SM_B1   (SM_B0 + BFRAG_CHUNK)    // 93184
#define SM_POW  SM_A0                    // epilogue staging (17920 B)
#define SM_TOTAL (SM_B1 + BFRAG_CHUNK)   // 111616

__device__ __align__(16) unsigned char g_Bfrag[BFRAG_BYTES];

// ---------------- helpers ----------------
__device__ __forceinline__ uint32_t smem_u32(const void* p) {
    uint32_t a;
    asm("{ .reg .u64 t; cvta.to.shared.u64 t, %1; cvt.u32.u64 %0, t; }"
        : "=r"(a) : "l"(p));
    return a;
}
__device__ __forceinline__ void ldmatrix4(uint32_t& r0, uint32_t& r1,
                                          uint32_t& r2, uint32_t& r3,
                                          uint32_t addr) {
    asm volatile("ldmatrix.sync.aligned.m8n8.x4.shared.b16 {%0,%1,%2,%3}, [%4];"
                 : "=r"(r0), "=r"(r1), "=r"(r2), "=r"(r3) : "r"(addr));
}
__device__ __forceinline__ void mma16816(float* c, uint32_t a0, uint32_t a1,
                                         uint32_t a2, uint32_t a3,
                                         uint32_t b0, uint32_t b1) {
    asm volatile(
        "mma.sync.aligned.m16n8k16.row.col.f32.bf16.bf16.f32 "
        "{%0,%1,%2,%3}, {%4,%5,%6,%7}, {%8,%9}, {%0,%1,%2,%3};"
        : "+f"(c[0]), "+f"(c[1]), "+f"(c[2]), "+f"(c[3])
        : "r"(a0), "r"(a1), "r"(a2), "r"(a3), "r"(b0), "r"(b1));
}

// W value at (phys index p within chunk c, output col m)
__device__ float wval(int c, int p, int m) {
    int l = p >> 1;
    int k = 64 * c + l + ((p & 1) ? 32 : 0);   // K permutation
    if (k >= DT || m >= 2 * NF) return 0.0f;
    int f = F0 + (m >> 1);
    double ang = 6.283185307179586476925286766559 * (double)f * (double)k / (double)DT;
    return (float)((m & 1) ? sin(ang) : cos(ang));
}

__global__ void build_Bfrag() {
    int t = blockIdx.x * blockDim.x + threadIdx.x;
    if (t >= NCHUNK * 4 * NTILES * 32) return;
    int lane = t & 31;
    int n = (t >> 5) % NTILES;
    int s = (t >> 5) / NTILES % 4;
    int c = t / (32 * NTILES * 4);

    int q = lane & 3, d = lane >> 2;
    int m  = 8 * n + d;
    int p0 = 16 * s + 2 * q;

    float w[4];
    w[0] = wval(c, p0,     m);
    w[1] = wval(c, p0 + 1, m);
    w[2] = wval(c, p0 + 8, m);
    w[3] = wval(c, p0 + 9, m);

    uint32_t h[4], lo[4];
    #pragma unroll
    for (int i = 0; i < 4; ++i) {
        __nv_bfloat16 hb = __float2bfloat16(w[i]);
        __nv_bfloat16 lb = __float2bfloat16(w[i] - __bfloat162float(hb));
        h[i]  = (uint32_t)__bfloat16_as_ushort(hb);
        lo[i] = (uint32_t)__bfloat16_as_ushort(lb);
    }
    uint4 v;
    v.x = h[0]  | (h[1]  << 16);
    v.y = h[2]  | (h[3]  << 16);
    v.z = lo[0] | (lo[1] << 16);
    v.w = lo[2] | (lo[3] << 16);
    ((uint4*)g_Bfrag)[((c * 4 + s) * NTILES + n) * 32 + lane] = v;
}

// prefetch one chunk's samples for this warp's 16 rows into registers
__device__ __forceinline__ void prefetch_rows(const unsigned char* smem, int chunk,
                                              int wid, int lane,
                                              float* x1, float* x2) {
    const bool g = (chunk < 4) || (lane < 12);   // k = 64c+32+lane < 300
    #pragma unroll
    for (int i = 0; i < 16; ++i) {
        const int r = wid + 8 * i;
        const float* p = *(const float* const*)(smem + SM_PTR + r * 8);
        x1[i] = __ldg(p + 64 * chunk + lane);    // k <= 287, always valid
        float v = 0.0f;
        if (g) v = __ldg(p + 64 * chunk + 32 + lane);
        x2[i] = v;
    }
}

// split to bf16 hi/lo and store this warp's 16 rows into an A buffer
__device__ __forceinline__ void convert_rows(unsigned char* smem, uint32_t abuf,
                                             int wid, int lane,
                                             const float* x1, const float* x2) {
    #pragma unroll
    for (int i = 0; i < 16; ++i) {
        const int r = wid + 8 * i;
        uint32_t hp, lp;
        asm("cvt.rn.bf16x2.f32 %0, %1, %2;" : "=r"(hp) : "f"(x2[i]), "f"(x1[i]));
        float h1 = __uint_as_float(hp << 16);
        float h2 = __uint_as_float(hp & 0xffff0000u);
        float l1 = x1[i] - h1, l2 = x2[i] - h2;
        asm("cvt.rn.bf16x2.f32 %0, %1, %2;" : "=r"(lp) : "f"(l2), "f"(l1));
        const unsigned o = (unsigned)(r * ROWPITCH + lane * 4);
        *(uint32_t*)(smem + abuf + o) = hp;
        *(uint32_t*)(smem + abuf + A_HALF + o) = lp;
    }
}

__device__ __forceinline__ void cpasync_B(uint32_t sbase, uint32_t bbuf,
                                          int chunk, int tid) {
    const unsigned char* src = g_Bfrag + chunk * BFRAG_CHUNK;
    for (int i = tid; i < BFRAG_CHUNK / 16; i += 256) {
        asm volatile("cp.async.cg.shared.global [%0], [%1], 16;"
                     :: "r"(sbase + bbuf + i * 16), "l"(src + i * 16));
    }
    asm volatile("cp.async.commit_group;" ::: "memory");
}

__global__ __launch_bounds__(256, 2)
void st_dft_hmma(const float* __restrict__ inp,
                 const int*   __restrict__ offs,
                 float*       __restrict__ out)
{
    extern __shared__ __align__(16) unsigned char smem[];
    const uint32_t sbase = smem_u32(smem);
    const int tid  = threadIdx.x;
    const int wid  = tid >> 5;
    const int lane = tid & 31;
    const int base = blockIdx.x * M_TILE;

    if (tid < M_TILE) {
        int crop = base + tid;
        *(const float**)(smem + SM_PTR + tid * 8) =
            inp + (size_t)(crop >> 6) * TT + offs[crop];
    }
    __syncthreads();

    float acc[NTILES * 4];
    #pragma unroll
    for (int i = 0; i < NTILES * 4; ++i) acc[i] = 0.0f;

    float x1[16], x2[16];

    // ---- prologue: stage chunk 0 ----
    prefetch_rows(smem, 0, wid, lane, x1, x2);
    cpasync_B(sbase, SM_B0, 0, tid);
    convert_rows(smem, SM_A0, wid, lane, x1, x2);
    asm volatile("cp.async.wait_group 0;" ::: "memory");
    __syncthreads();

    const uint32_t lane_a = (uint32_t)((lane & 15) * ROWPITCH + ((lane >> 4) << 4)
                                       + 16 * wid * ROWPITCH);

    #pragma unroll 1
    for (int c = 0; c < NCHUNK; ++c) {
        const uint32_t abuf = (c & 1) ? SM_A1 : SM_A0;
        const uint32_t bbuf = (c & 1) ? SM_B1 : SM_B0;
        const uint32_t nabuf = (c & 1) ? SM_A0 : SM_A1;
        const uint32_t nbbuf = (c & 1) ? SM_B0 : SM_B1;

        // issue next chunk's loads before the MMAs (latency hidden under HMMA)
        if (c < NCHUNK - 1) {
            prefetch_rows(smem, c + 1, wid, lane, x1, x2);
            cpasync_B(sbase, nbbuf, c + 1, tid);
        }

        // ---- MMAs for chunk c ----
        const uint32_t arow = sbase + abuf + lane_a;
        #pragma unroll
        for (int s = 0; s < 4; ++s) {
            uint32_t ah0, ah1, ah2, ah3, al0, al1, al2, al3;
            ldmatrix4(ah0, ah1, ah2, ah3, arow + 32 * s);
            ldmatrix4(al0, al1, al2, al3, arow + A_HALF + 32 * s);
            #pragma unroll
            for (int n = 0; n < NTILES; ++n) {
                uint4 b = *(const uint4*)(smem + bbuf
                          + (((s * NTILES + n) * 32 + lane) << 4));
                mma16816(acc + n * 4, ah0, ah1, ah2, ah3, b.x, b.y);  // AhiBhi
                mma16816(acc + n * 4, ah0, ah1, ah2, ah3, b.z, b.w);  // AhiBlo
                mma16816(acc + n * 4, al0, al1, al2, al3, b.x, b.y);  // AloBhi
            }
        }

        if (c < NCHUNK - 1)
            convert_rows(smem, nabuf, wid, lane, x1, x2);

        asm volatile("cp.async.wait_group 0;" ::: "memory");
        __syncthreads();
    }

    // --- epilogue: power, band-normalize, stage, coalesced store ---
    {
        const int q = lane & 3;
        const int rA = 16 * wid + (lane >> 2);
        const int rB = rA + 8;

        float pA[NTILES], pB[NTILES];
        float sA = 0.0f, sB = 0.0f;
        #pragma unroll
        for (int n = 0; n < NTILES; ++n) {
            pA[n] = fmaf(acc[n*4+0], acc[n*4+0], acc[n*4+1] * acc[n*4+1]);
            pB[n] = fmaf(acc[n*4+2], acc[n*4+2], acc[n*4+3] * acc[n*4+3]);
            sA += pA[n];  sB += pB[n];   // pad col j=35 contributes exactly 0
        }
        sA += __shfl_xor_sync(0xffffffffu, sA, 1);
        sA += __shfl_xor_sync(0xffffffffu, sA, 2);
        sB += __shfl_xor_sync(0xffffffffu, sB, 1);
        sB += __shfl_xor_sync(0xffffffffu, sB, 2);
        const float iA = 1.0f / sA, iB = 1.0f / sB;

        float* pw = (float*)(smem + SM_POW);
        #pragma unroll
        for (int n = 0; n < NTILES; ++n) {
            int j = 4 * n + q;
            if (j < NF) {
                pw[rA * NF + j] = pA[n] * iA;
                pw[rB * NF + j] = pB[n] * iB;
            }
        }
    }
    __syncthreads();

    {
        uint4* o = (uint4*)(out + (size_t)base * NF);
        const uint4* s = (const uint4*)(smem + SM_POW);
        #pragma unroll
        for (int i = tid; i < (M_TILE * NF * 4) / 16; i += 256) o[i] = s[i];
    }
}

extern "C" void kernel_launch(void* const* d_in, const int* in_sizes, int n_in,
                              void* d_out, int out_size)
{
    const float* inp  = (const float*)d_in[0];   // [B, C, T] float32
    const int*   offs = (const int*)  d_in[1];   // [B, C, K] int32
    float*       out  = (float*)d_out;           // [B, C, K, NF] float32

    (void)in_sizes; (void)n_in; (void)out_size;

    static int configured = 0;
    if (!configured) {
        cudaFuncSetAttribute(st_dft_hmma,
                             cudaFuncAttributeMaxDynamicSharedMemorySize, SM_TOTAL);
        configured = 1;
    }

    build_Bfrag<<<(NCHUNK * 4 * NTILES * 32 + 255) / 256, 256>>>();
    st_dft_hmma<<<NCROP / M_TILE, 256, SM_TOTAL>>>(inp, offs, out);
}

// round 14
// speedup vs baseline: 2.2929x; 1.0503x over previous
#include <cuda_runtime.h>
#include <cuda_bf16.h>
#include <math.h>
#include <stdint.h>

// ---------------- problem constants ----------------
#define BB 256
#define CC 16
#define TT 9000
#define KK 64
#define DT 300
#define F0 7
#define NF 35
#define NCROP (BB*CC*KK)      // 262144

// ---------------- tile constants ----------------
#define M_TILE   128          // crops per CTA (4 warps x 32 rows)
#define NTILES   9            // 72 cols / 8
#define NCHUNK   5            // K = 5 * 64 (logical 300, rest zero)
#define ROWPITCH 144          // bytes per A row in SMEM (64 bf16 + 16 pad)
#define A_HALF   (M_TILE*ROWPITCH)       // 18432 (one hi or lo plane)

// B fragments: [chunk][kstep 4][ntile 9][lane 32] x uint4{bhi0,bhi1,blo0,blo1}
#define BFRAG_CHUNK (4*NTILES*32*16)     // 18432 B
#define BFRAG_BYTES (NCHUNK*BFRAG_CHUNK) // 92160 B

// ---------------- dynamic SMEM layout ----------------
#define SM_PTR  0                        // 128 crop pointers (8 B each)
#define SM_A0   1024                     // buf0: hi @ +0, lo @ +A_HALF
#define SM_A1   (SM_A0 + 2*A_HALF)       // 37888
#define SM_B0   (SM_A1 + 2*A_HALF)       // 74752
#define SM_B1   (SM_B0 + BFRAG_CHUNK)    // 93184
#define SM_POW  SM_A0                    // epilogue staging (17920 B)
#define SM_TOTAL (SM_B1 + BFRAG_CHUNK)   // 111616

__device__ __align__(16) unsigned char g_Bfrag[BFRAG_BYTES];

// ---------------- helpers ----------------
__device__ __forceinline__ uint32_t smem_u32(const void* p) {
    uint32_t a;
    asm("{ .reg .u64 t; cvta.to.shared.u64 t, %1; cvt.u32.u64 %0, t; }"
        : "=r"(a) : "l"(p));
    return a;
}
__device__ __forceinline__ void ldmatrix4(uint32_t& r0, uint32_t& r1,
                                          uint32_t& r2, uint32_t& r3,
                                          uint32_t addr) {
    asm volatile("ldmatrix.sync.aligned.m8n8.x4.shared.b16 {%0,%1,%2,%3}, [%4];"
                 : "=r"(r0), "=r"(r1), "=r"(r2), "=r"(r3) : "r"(addr));
}
__device__ __forceinline__ void mma16816(float* c, uint32_t a0, uint32_t a1,
                                         uint32_t a2, uint32_t a3,
                                         uint32_t b0, uint32_t b1) {
    asm volatile(
        "mma.sync.aligned.m16n8k16.row.col.f32.bf16.bf16.f32 "
        "{%0,%1,%2,%3}, {%4,%5,%6,%7}, {%8,%9}, {%0,%1,%2,%3};"
        : "+f"(c[0]), "+f"(c[1]), "+f"(c[2]), "+f"(c[3])
        : "r"(a0), "r"(a1), "r"(a2), "r"(a3), "r"(b0), "r"(b1));
}

// W value at (phys index p within chunk c, output col m)
__device__ float wval(int c, int p, int m) {
    int l = p >> 1;
    int k = 64 * c + l + ((p & 1) ? 32 : 0);   // K permutation
    if (k >= DT || m >= 2 * NF) return 0.0f;
    int f = F0 + (m >> 1);
    double ang = 6.283185307179586476925286766559 * (double)f * (double)k / (double)DT;
    return (float)((m & 1) ? sin(ang) : cos(ang));
}

__global__ void build_Bfrag() {
    int t = blockIdx.x * blockDim.x + threadIdx.x;
    if (t >= NCHUNK * 4 * NTILES * 32) return;
    int lane = t & 31;
    int n = (t >> 5) % NTILES;
    int s = (t >> 5) / NTILES % 4;
    int c = t / (32 * NTILES * 4);

    int q = lane & 3, d = lane >> 2;
    int m  = 8 * n + d;
    int p0 = 16 * s + 2 * q;

    float w[4];
    w[0] = wval(c, p0,     m);
    w[1] = wval(c, p0 + 1, m);
    w[2] = wval(c, p0 + 8, m);
    w[3] = wval(c, p0 + 9, m);

    uint32_t h[4], lo[4];
    #pragma unroll
    for (int i = 0; i < 4; ++i) {
        __nv_bfloat16 hb = __float2bfloat16(w[i]);
        __nv_bfloat16 lb = __float2bfloat16(w[i] - __bfloat162float(hb));
        h[i]  = (uint32_t)__bfloat16_as_ushort(hb);
        lo[i] = (uint32_t)__bfloat16_as_ushort(lb);
    }
    uint4 v;
    v.x = h[0]  | (h[1]  << 16);
    v.y = h[2]  | (h[3]  << 16);
    v.z = lo[0] | (lo[1] << 16);
    v.w = lo[2] | (lo[3] << 16);
    ((uint4*)g_Bfrag)[((c * 4 + s) * NTILES + n) * 32 + lane] = v;
}

// prefetch one chunk's samples for this warp's 32 rows into registers
__device__ __forceinline__ void prefetch_rows(const unsigned char* smem, int chunk,
                                              int wid, int lane,
                                              float* x1, float* x2) {
    const bool g = (chunk < 4) || (lane < 12);   // k = 64c+32+lane < 300
    #pragma unroll
    for (int i = 0; i < 32; ++i) {
        const int r = wid * 32 + i;
        const float* p = *(const float* const*)(smem + SM_PTR + r * 8);
        x1[i] = __ldg(p + 64 * chunk + lane);    // k <= 287, always valid
        float v = 0.0f;
        if (g) v = __ldg(p + 64 * chunk + 32 + lane);
        x2[i] = v;
    }
}

// split to bf16 hi/lo and store this warp's 32 rows into an A buffer
__device__ __forceinline__ void convert_rows(unsigned char* smem, uint32_t abuf,
                                             int wid, int lane,
                                             const float* x1, const float* x2) {
    #pragma unroll
    for (int i = 0; i < 32; ++i) {
        const int r = wid * 32 + i;
        uint32_t hp, lp;
        asm("cvt.rn.bf16x2.f32 %0, %1, %2;" : "=r"(hp) : "f"(x2[i]), "f"(x1[i]));
        float h1 = __uint_as_float(hp << 16);
        float h2 = __uint_as_float(hp & 0xffff0000u);
        float l1 = x1[i] - h1, l2 = x2[i] - h2;
        asm("cvt.rn.bf16x2.f32 %0, %1, %2;" : "=r"(lp) : "f"(l2), "f"(l1));
        const unsigned o = (unsigned)(r * ROWPITCH + lane * 4);
        *(uint32_t*)(smem + abuf + o) = hp;
        *(uint32_t*)(smem + abuf + A_HALF + o) = lp;
    }
}

__device__ __forceinline__ void cpasync_B(uint32_t sbase, uint32_t bbuf,
                                          int chunk, int tid) {
    const unsigned char* src = g_Bfrag + chunk * BFRAG_CHUNK;
    for (int i = tid; i < BFRAG_CHUNK / 16; i += 128) {
        asm volatile("cp.async.cg.shared.global [%0], [%1], 16;"
                     :: "r"(sbase + bbuf + i * 16), "l"(src + i * 16));
    }
    asm volatile("cp.async.commit_group;" ::: "memory");
}

__global__ __launch_bounds__(128, 2)
void st_dft_hmma(const float* __restrict__ inp,
                 const int*   __restrict__ offs,
                 float*       __restrict__ out)
{
    extern __shared__ __align__(16) unsigned char smem[];
    const uint32_t sbase = smem_u32(smem);
    const int tid  = threadIdx.x;
    const int wid  = tid >> 5;       // 0..3, owns rows [32w, 32w+32)
    const int lane = tid & 31;
    const int base = blockIdx.x * M_TILE;

    if (tid < M_TILE) {
        int crop = base + tid;
        *(const float**)(smem + SM_PTR + tid * 8) =
            inp + (size_t)(crop >> 6) * TT + offs[crop];
    }
    __syncthreads();

    // acc[tile][n][4] : tile0 = rows 32w..+15, tile1 = rows 32w+16..+31
    float acc[2 * NTILES * 4];
    #pragma unroll
    for (int i = 0; i < 2 * NTILES * 4; ++i) acc[i] = 0.0f;

    float x1[32], x2[32];

    // ---- prologue: stage chunk 0 ----
    prefetch_rows(smem, 0, wid, lane, x1, x2);
    cpasync_B(sbase, SM_B0, 0, tid);
    convert_rows(smem, SM_A0, wid, lane, x1, x2);
    asm volatile("cp.async.wait_group 0;" ::: "memory");
    __syncthreads();

    // ldmatrix row base for the two 16-row M-tiles of this warp
    const uint32_t lane_a = (uint32_t)((32 * wid + (lane & 15)) * ROWPITCH
                                       + ((lane >> 4) << 4));

    #pragma unroll 1
    for (int c = 0; c < NCHUNK; ++c) {
        const uint32_t abuf = (c & 1) ? SM_A1 : SM_A0;
        const uint32_t bbuf = (c & 1) ? SM_B1 : SM_B0;
        const uint32_t nabuf = (c & 1) ? SM_A0 : SM_A1;
        const uint32_t nbbuf = (c & 1) ? SM_B0 : SM_B1;

        // issue next chunk's loads before the MMAs (latency hidden under HMMA)
        if (c < NCHUNK - 1) {
            prefetch_rows(smem, c + 1, wid, lane, x1, x2);
            cpasync_B(sbase, nbbuf, c + 1, tid);
        }

        // ---- MMAs for chunk c: each B uint4 feeds 6 MMAs ----
        const uint32_t arow0 = sbase + abuf + lane_a;             // tile0
        const uint32_t arow1 = arow0 + 16 * ROWPITCH;             // tile1
        #pragma unroll
        for (int s = 0; s < 4; ++s) {
            uint32_t ah0[4], al0[4], ah1[4], al1[4];
            ldmatrix4(ah0[0], ah0[1], ah0[2], ah0[3], arow0 + 32 * s);
            ldmatrix4(al0[0], al0[1], al0[2], al0[3], arow0 + A_HALF + 32 * s);
            ldmatrix4(ah1[0], ah1[1], ah1[2], ah1[3], arow1 + 32 * s);
            ldmatrix4(al1[0], al1[1], al1[2], al1[3], arow1 + A_HALF + 32 * s);
            #pragma unroll
            for (int n = 0; n < NTILES; ++n) {
                uint4 b = *(const uint4*)(smem + bbuf
                          + (((s * NTILES + n) * 32 + lane) << 4));
                float* a0 = acc + n * 4;
                float* a1 = acc + (NTILES + n) * 4;
                mma16816(a0, ah0[0], ah0[1], ah0[2], ah0[3], b.x, b.y); // hi*Bhi
                mma16816(a1, ah1[0], ah1[1], ah1[2], ah1[3], b.x, b.y);
                mma16816(a0, ah0[0], ah0[1], ah0[2], ah0[3], b.z, b.w); // hi*Blo
                mma16816(a1, ah1[0], ah1[1], ah1[2], ah1[3], b.z, b.w);
                mma16816(a0, al0[0], al0[1], al0[2], al0[3], b.x, b.y); // lo*Bhi
                mma16816(a1, al1[0], al1[1], al1[2], al1[3], b.x, b.y);
            }
        }

        if (c < NCHUNK - 1)
            convert_rows(smem, nabuf, wid, lane, x1, x2);

        asm volatile("cp.async.wait_group 0;" ::: "memory");
        __syncthreads();
    }

    // --- epilogue: power, band-normalize, stage, coalesced store ---
    {
        const int q = lane & 3;
        float* pw = (float*)(smem + SM_POW);

        #pragma unroll
        for (int t = 0; t < 2; ++t) {
            const int rA = 32 * wid + 16 * t + (lane >> 2);
            const int rB = rA + 8;
            const float* a = acc + t * NTILES * 4;

            float pA[NTILES], pB[NTILES];
            float sA = 0.0f, sB = 0.0f;
            #pragma unroll
            for (int n = 0; n < NTILES; ++n) {
                pA[n] = fmaf(a[n*4+0], a[n*4+0], a[n*4+1] * a[n*4+1]);
                pB[n] = fmaf(a[n*4+2], a[n*4+2], a[n*4+3] * a[n*4+3]);
                sA += pA[n];  sB += pB[n];   // pad col j=35 contributes 0
            }
            sA += __shfl_xor_sync(0xffffffffu, sA, 1);
            sA += __shfl_xor_sync(0xffffffffu, sA, 2);
            sB += __shfl_xor_sync(0xffffffffu, sB, 1);
            sB += __shfl_xor_sync(0xffffffffu, sB, 2);
            const float iA = 1.0f / sA, iB = 1.0f / sB;

            #pragma unroll
            for (int n = 0; n < NTILES; ++n) {
                int j = 4 * n + q;
                if (j < NF) {
                    pw[rA * NF + j] = pA[n] * iA;
                    pw[rB * NF + j] = pB[n] * iB;
                }
            }
        }
    }
    __syncthreads();

    {
        uint4* o = (uint4*)(out + (size_t)base * NF);
        const uint4* s = (const uint4*)(smem + SM_POW);
        #pragma unroll 2
        for (int i = tid; i < (M_TILE * NF * 4) / 16; i += 128) o[i] = s[i];
    }
}

extern "C" void kernel_launch(void* const* d_in, const int* in_sizes, int n_in,
                              void* d_out, int out_size)
{
    const float* inp  = (const float*)d_in[0];   // [B, C, T] float32
    const int*   offs = (const int*)  d_in[1];   // [B, C, K] int32
    float*       out  = (float*)d_out;           // [B, C, K, NF] float32

    (void)in_sizes; (void)n_in; (void)out_size;

    static int configured = 0;
    if (!configured) {
        cudaFuncSetAttribute(st_dft_hmma,
                             cudaFuncAttributeMaxDynamicSharedMemorySize, SM_TOTAL);
        configured = 1;
    }

    build_Bfrag<<<(NCHUNK * 4 * NTILES * 32 + 255) / 256, 256>>>();
    st_dft_hmma<<<NCROP / M_TILE, 128, SM_TOTAL>>>(inp, offs, out);
}

// round 15
// speedup vs baseline: 2.3944x; 1.0443x over previous
#include <cuda_runtime.h>
#include <cuda_bf16.h>
#include <math.h>
#include <stdint.h>

// ---------------- problem constants ----------------
#define BB 256
#define CC 16
#define TT 9000
#define KK 64
#define DT 300
#define F0 7
#define NF 35
#define NCROP (BB*CC*KK)      // 262144

// ---------------- tile constants ----------------
#define M_TILE   128          // crops per CTA (4 warps x 32 rows)
#define NTILES   9            // 72 cols / 8
#define NCHUNK   5            // K = 5 * 64 (logical 300, rest zero)
#define ROWPITCH 144          // bytes per A row in SMEM (64 bf16 + 16 pad)
#define A_HALF   (M_TILE*ROWPITCH)       // 18432 (one hi or lo plane)

// B fragments: [chunk][kstep 4][ntile 9][lane 32] x uint4{bhi0,bhi1,blo0,blo1}
#define BFRAG_CHUNK (4*NTILES*32*16)     // 18432 B
#define BFRAG_BYTES (NCHUNK*BFRAG_CHUNK) // 92160 B

// ---------------- dynamic SMEM layout ----------------
#define SM_PTR  0                        // 128 crop pointers (8 B each)
#define SM_A0   1024                     // buf0: hi @ +0, lo @ +A_HALF
#define SM_A1   (SM_A0 + 2*A_HALF)       // 37888
#define SM_B0   (SM_A1 + 2*A_HALF)       // 74752
#define SM_B1   (SM_B0 + BFRAG_CHUNK)    // 93184
#define SM_POW  SM_A0                    // epilogue staging (17920 B)
#define SM_TOTAL (SM_B1 + BFRAG_CHUNK)   // 111616

__device__ __align__(16) unsigned char g_Bfrag[BFRAG_BYTES];

// ---------------- helpers ----------------
__device__ __forceinline__ uint32_t smem_u32(const void* p) {
    uint32_t a;
    asm("{ .reg .u64 t; cvta.to.shared.u64 t, %1; cvt.u32.u64 %0, t; }"
        : "=r"(a) : "l"(p));
    return a;
}
__device__ __forceinline__ void ldmatrix4(uint32_t& r0, uint32_t& r1,
                                          uint32_t& r2, uint32_t& r3,
                                          uint32_t addr) {
    asm volatile("ldmatrix.sync.aligned.m8n8.x4.shared.b16 {%0,%1,%2,%3}, [%4];"
                 : "=r"(r0), "=r"(r1), "=r"(r2), "=r"(r3) : "r"(addr));
}
__device__ __forceinline__ void mma16816(float* c, uint32_t a0, uint32_t a1,
                                         uint32_t a2, uint32_t a3,
                                         uint32_t b0, uint32_t b1) {
    asm volatile(
        "mma.sync.aligned.m16n8k16.row.col.f32.bf16.bf16.f32 "
        "{%0,%1,%2,%3}, {%4,%5,%6,%7}, {%8,%9}, {%0,%1,%2,%3};"
        : "+f"(c[0]), "+f"(c[1]), "+f"(c[2]), "+f"(c[3])
        : "r"(a0), "r"(a1), "r"(a2), "r"(a3), "r"(b0), "r"(b1));
}

// W value at (phys index p within chunk c, output col m).
// Chunks 0-3: pairwise permutation phys(2l)=k 64c+l, phys(2l+1)=64c+32+l.
// Chunk 4: identity phys p = k 256+p (valid k<300 all land in steps 0-2,
//          so k-step 3 of chunk 4 is exactly zero and is skipped).
__device__ float wval(int c, int p, int m) {
    int k;
    if (c == 4) k = 256 + p;
    else        k = 64 * c + (p >> 1) + ((p & 1) ? 32 : 0);
    if (k >= DT || m >= 2 * NF) return 0.0f;
    int f = F0 + (m >> 1);
    double ang = 6.283185307179586476925286766559 * (double)f * (double)k / (double)DT;
    return (float)((m & 1) ? sin(ang) : cos(ang));
}

__global__ void build_Bfrag() {
    int t = blockIdx.x * blockDim.x + threadIdx.x;
    if (t >= NCHUNK * 4 * NTILES * 32) return;
    int lane = t & 31;
    int n = (t >> 5) % NTILES;
    int s = (t >> 5) / NTILES % 4;
    int c = t / (32 * NTILES * 4);

    int q = lane & 3, d = lane >> 2;
    int m  = 8 * n + d;
    int p0 = 16 * s + 2 * q;

    float w[4];
    w[0] = wval(c, p0,     m);
    w[1] = wval(c, p0 + 1, m);
    w[2] = wval(c, p0 + 8, m);
    w[3] = wval(c, p0 + 9, m);

    uint32_t h[4], lo[4];
    #pragma unroll
    for (int i = 0; i < 4; ++i) {
        __nv_bfloat16 hb = __float2bfloat16(w[i]);
        __nv_bfloat16 lb = __float2bfloat16(w[i] - __bfloat162float(hb));
        h[i]  = (uint32_t)__bfloat16_as_ushort(hb);
        lo[i] = (uint32_t)__bfloat16_as_ushort(lb);
    }
    uint4 v;
    v.x = h[0]  | (h[1]  << 16);
    v.y = h[2]  | (h[3]  << 16);
    v.z = lo[0] | (lo[1] << 16);
    v.w = lo[2] | (lo[3] << 16);
    ((uint4*)g_Bfrag)[((c * 4 + s) * NTILES + n) * 32 + lane] = v;
}

// prefetch one chunk's samples for this warp's 32 rows into registers
__device__ __forceinline__ void prefetch_rows(const unsigned char* smem, int chunk,
                                              int wid, int lane,
                                              float* x1, float* x2) {
    if (chunk == 4) {
        const bool g = (lane <= 21);          // k = 256+2l(+1) <= 299
        #pragma unroll
        for (int i = 0; i < 32; ++i) {
            const int r = wid * 32 + i;
            const float* p = *(const float* const*)(smem + SM_PTR + r * 8);
            x1[i] = g ? __ldg(p + 256 + 2 * lane) : 0.0f;
            x2[i] = g ? __ldg(p + 257 + 2 * lane) : 0.0f;
        }
    } else {
        #pragma unroll
        for (int i = 0; i < 32; ++i) {
            const int r = wid * 32 + i;
            const float* p = *(const float* const*)(smem + SM_PTR + r * 8);
            x1[i] = __ldg(p + 64 * chunk + lane);        // k <= 255, valid
            x2[i] = __ldg(p + 64 * chunk + 32 + lane);   // k <= 255, valid
        }
    }
}

// split 16 rows (half=0: rows 0-15, half=1: rows 16-31) to bf16 hi/lo planes
__device__ __forceinline__ void convert_rows16(unsigned char* smem, uint32_t abuf,
                                               int wid, int lane,
                                               const float* x1, const float* x2,
                                               int half) {
    #pragma unroll
    for (int i = 0; i < 16; ++i) {
        const int idx = half * 16 + i;
        const int r = wid * 32 + idx;
        uint32_t hp, lp;
        asm("cvt.rn.bf16x2.f32 %0, %1, %2;" : "=r"(hp) : "f"(x2[idx]), "f"(x1[idx]));
        float h1 = __uint_as_float(hp << 16);
        float h2 = __uint_as_float(hp & 0xffff0000u);
        float l1 = x1[idx] - h1, l2 = x2[idx] - h2;
        asm("cvt.rn.bf16x2.f32 %0, %1, %2;" : "=r"(lp) : "f"(l2), "f"(l1));
        const unsigned o = (unsigned)(r * ROWPITCH + lane * 4);
        *(uint32_t*)(smem + abuf + o) = hp;
        *(uint32_t*)(smem + abuf + A_HALF + o) = lp;
    }
}

__device__ __forceinline__ void cpasync_B(uint32_t sbase, uint32_t bbuf,
                                          int chunk, int tid) {
    const unsigned char* src = g_Bfrag + chunk * BFRAG_CHUNK;
    for (int i = tid; i < BFRAG_CHUNK / 16; i += 128) {
        asm volatile("cp.async.cg.shared.global [%0], [%1], 16;"
                     :: "r"(sbase + bbuf + i * 16), "l"(src + i * 16));
    }
    asm volatile("cp.async.commit_group;" ::: "memory");
}

// one k-step: 4 ldmatrix + 54 MMAs (2 m-tiles x 9 n-tiles x 3 split products)
__device__ __forceinline__ void mma_step(const unsigned char* smem,
                                         uint32_t arow0, uint32_t arow1,
                                         uint32_t bbuf, int s, int lane,
                                         float* acc) {
    uint32_t ah0[4], al0[4], ah1[4], al1[4];
    ldmatrix4(ah0[0], ah0[1], ah0[2], ah0[3], arow0 + 32 * s);
    ldmatrix4(al0[0], al0[1], al0[2], al0[3], arow0 + A_HALF + 32 * s);
    ldmatrix4(ah1[0], ah1[1], ah1[2], ah1[3], arow1 + 32 * s);
    ldmatrix4(al1[0], al1[1], al1[2], al1[3], arow1 + A_HALF + 32 * s);
    #pragma unroll
    for (int n = 0; n < NTILES; ++n) {
        uint4 b = *(const uint4*)(smem + bbuf + (((s * NTILES + n) * 32 + lane) << 4));
        float* a0 = acc + n * 4;
        float* a1 = acc + (NTILES + n) * 4;
        mma16816(a0, ah0[0], ah0[1], ah0[2], ah0[3], b.x, b.y);   // hi*Bhi
        mma16816(a1, ah1[0], ah1[1], ah1[2], ah1[3], b.x, b.y);
        mma16816(a0, ah0[0], ah0[1], ah0[2], ah0[3], b.z, b.w);   // hi*Blo
        mma16816(a1, ah1[0], ah1[1], ah1[2], ah1[3], b.z, b.w);
        mma16816(a0, al0[0], al0[1], al0[2], al0[3], b.x, b.y);   // lo*Bhi
        mma16816(a1, al1[0], al1[1], al1[2], al1[3], b.x, b.y);
    }
}

__global__ __launch_bounds__(128, 2)
void st_dft_hmma(const float* __restrict__ inp,
                 const int*   __restrict__ offs,
                 float*       __restrict__ out)
{
    extern __shared__ __align__(16) unsigned char smem[];
    const uint32_t sbase = smem_u32(smem);
    const int tid  = threadIdx.x;
    const int wid  = tid >> 5;       // 0..3, owns rows [32w, 32w+32)
    const int lane = tid & 31;
    const int base = blockIdx.x * M_TILE;

    if (tid < M_TILE) {
        int crop = base + tid;
        *(const float**)(smem + SM_PTR + tid * 8) =
            inp + (size_t)(crop >> 6) * TT + offs[crop];
    }
    __syncthreads();

    float acc[2 * NTILES * 4];
    #pragma unroll
    for (int i = 0; i < 2 * NTILES * 4; ++i) acc[i] = 0.0f;

    float x1[32], x2[32];

    // ---- prologue: stage chunk 0 (serial once) ----
    prefetch_rows(smem, 0, wid, lane, x1, x2);
    cpasync_B(sbase, SM_B0, 0, tid);
    convert_rows16(smem, SM_A0, wid, lane, x1, x2, 0);
    convert_rows16(smem, SM_A0, wid, lane, x1, x2, 1);
    asm volatile("cp.async.wait_group 0;" ::: "memory");
    __syncthreads();

    const uint32_t lane_a = (uint32_t)((32 * wid + (lane & 15)) * ROWPITCH
                                       + ((lane >> 4) << 4));

    // ---- chunks 0..3: 4 k-steps, convert(c+1) interleaved at s=2,3 ----
    #pragma unroll 1
    for (int c = 0; c < NCHUNK - 1; ++c) {
        const uint32_t abuf = (c & 1) ? SM_A1 : SM_A0;
        const uint32_t bbuf = (c & 1) ? SM_B1 : SM_B0;
        const uint32_t nabuf = (c & 1) ? SM_A0 : SM_A1;
        const uint32_t nbbuf = (c & 1) ? SM_B0 : SM_B1;

        // issue next chunk's loads; ~2 MMA steps of latency cover before use
        prefetch_rows(smem, c + 1, wid, lane, x1, x2);
        cpasync_B(sbase, nbbuf, c + 1, tid);

        const uint32_t arow0 = sbase + abuf + lane_a;
        const uint32_t arow1 = arow0 + 16 * ROWPITCH;

        mma_step(smem, arow0, arow1, bbuf, 0, lane, acc);
        mma_step(smem, arow0, arow1, bbuf, 1, lane, acc);
        mma_step(smem, arow0, arow1, bbuf, 2, lane, acc);
        convert_rows16(smem, nabuf, wid, lane, x1, x2, 0);   // interleaves w/ s=2
        mma_step(smem, arow0, arow1, bbuf, 3, lane, acc);
        convert_rows16(smem, nabuf, wid, lane, x1, x2, 1);   // interleaves w/ s=3

        asm volatile("cp.async.wait_group 0;" ::: "memory");
        __syncthreads();
    }

    // ---- chunk 4: only 3 k-steps carry data (identity permutation) ----
    {
        const uint32_t arow0 = sbase + SM_A0 + lane_a;       // chunk 4 -> buf 0
        const uint32_t arow1 = arow0 + 16 * ROWPITCH;
        mma_step(smem, arow0, arow1, SM_B0, 0, lane, acc);
        mma_step(smem, arow0, arow1, SM_B0, 1, lane, acc);
        mma_step(smem, arow0, arow1, SM_B0, 2, lane, acc);
    }
    __syncthreads();   // all mma reads done before reusing A buffer for staging

    // --- epilogue: power, band-normalize, stage, coalesced store ---
    {
        const int q = lane & 3;
        float* pw = (float*)(smem + SM_POW);

        #pragma unroll
        for (int t = 0; t < 2; ++t) {
            const int rA = 32 * wid + 16 * t + (lane >> 2);
            const int rB = rA + 8;
            const float* a = acc + t * NTILES * 4;

            float pA[NTILES], pB[NTILES];
            float sA = 0.0f, sB = 0.0f;
            #pragma unroll
            for (int n = 0; n < NTILES; ++n) {
                pA[n] = fmaf(a[n*4+0], a[n*4+0], a[n*4+1] * a[n*4+1]);
                pB[n] = fmaf(a[n*4+2], a[n*4+2], a[n*4+3] * a[n*4+3]);
                sA += pA[n];  sB += pB[n];   // pad col j=35 contributes 0
            }
            sA += __shfl_xor_sync(0xffffffffu, sA, 1);
            sA += __shfl_xor_sync(0xffffffffu, sA, 2);
            sB += __shfl_xor_sync(0xffffffffu, sB, 1);
            sB += __shfl_xor_sync(0xffffffffu, sB, 2);
            const float iA = 1.0f / sA, iB = 1.0f / sB;

            #pragma unroll
            for (int n = 0; n < NTILES; ++n) {
                int j = 4 * n + q;
                if (j < NF) {
                    pw[rA * NF + j] = pA[n] * iA;
                    pw[rB * NF + j] = pB[n] * iB;
                }
            }
        }
    }
    __syncthreads();

    {
        uint4* o = (uint4*)(out + (size_t)base * NF);
        const uint4* s = (const uint4*)(smem + SM_POW);
        #pragma unroll 2
        for (int i = tid; i < (M_TILE * NF * 4) / 16; i += 128) o[i] = s[i];
    }
}

extern "C" void kernel_launch(void* const* d_in, const int* in_sizes, int n_in,
                              void* d_out, int out_size)
{
    const float* inp  = (const float*)d_in[0];   // [B, C, T] float32
    const int*   offs = (const int*)  d_in[1];   // [B, C, K] int32
    float*       out  = (float*)d_out;           // [B, C, K, NF] float32

    (void)in_sizes; (void)n_in; (void)out_size;

    static int configured = 0;
    if (!configured) {
        cudaFuncSetAttribute(st_dft_hmma,
                             cudaFuncAttributeMaxDynamicSharedMemorySize, SM_TOTAL);
        configured = 1;
    }

    build_Bfrag<<<(NCHUNK * 4 * NTILES * 32 + 255) / 256, 256>>>();
    st_dft_hmma<<<NCROP / M_TILE, 128, SM_TOTAL>>>(inp, offs, out);
}

// round 16
// speedup vs baseline: 3.1008x; 1.2950x over previous
#include <cuda_runtime.h>
#include <cuda_fp16.h>
#include <math.h>
#include <stdint.h>

// ---------------- problem constants ----------------
#define BB 256
#define CC 16
#define TT 9000
#define KK 64
#define DT 300
#define F0 7
#define NF 35
#define NCROP (BB*CC*KK)      // 262144

// ---------------- tile constants ----------------
#define M_TILE   128          // crops per CTA (4 warps x 32 rows)
#define NTILES   9            // 72 cols / 8
#define NCHUNK   5            // K = 5 * 64 (logical 300, rest zero)
#define ROWPITCH 144          // bytes per A row in SMEM (64 fp16 + 16 pad)
#define A_HALF   (M_TILE*ROWPITCH)       // 18432 (one hi or lo plane)

// B fragments: [chunk][kstep 4][ntile 9][lane 32] x uint2{b0,b1} (fp16)
#define BFRAG_CHUNK (4*NTILES*32*8)      // 9216 B
#define BFRAG_BYTES (NCHUNK*BFRAG_CHUNK) // 46080 B

// ---------------- dynamic SMEM layout ----------------
#define SM_PTR  0                        // 128 crop pointers (8 B each)
#define SM_A0   1024                     // buf0: hi @ +0, lo @ +A_HALF
#define SM_A1   (SM_A0 + 2*A_HALF)       // 37888
#define SM_B0   (SM_A1 + 2*A_HALF)       // 74752
#define SM_B1   (SM_B0 + BFRAG_CHUNK)    // 83968
#define SM_POW  SM_A0                    // epilogue staging (17920 B)
#define SM_TOTAL (SM_B1 + BFRAG_CHUNK)   // 93184

__device__ __align__(16) unsigned char g_Bfrag[BFRAG_BYTES];

// ---------------- helpers ----------------
__device__ __forceinline__ uint32_t smem_u32(const void* p) {
    uint32_t a;
    asm("{ .reg .u64 t; cvta.to.shared.u64 t, %1; cvt.u32.u64 %0, t; }"
        : "=r"(a) : "l"(p));
    return a;
}
__device__ __forceinline__ void ldmatrix4(uint32_t& r0, uint32_t& r1,
                                          uint32_t& r2, uint32_t& r3,
                                          uint32_t addr) {
    asm volatile("ldmatrix.sync.aligned.m8n8.x4.shared.b16 {%0,%1,%2,%3}, [%4];"
                 : "=r"(r0), "=r"(r1), "=r"(r2), "=r"(r3) : "r"(addr));
}
__device__ __forceinline__ void mma16816(float* c, uint32_t a0, uint32_t a1,
                                         uint32_t a2, uint32_t a3,
                                         uint32_t b0, uint32_t b1) {
    asm volatile(
        "mma.sync.aligned.m16n8k16.row.col.f32.f16.f16.f32 "
        "{%0,%1,%2,%3}, {%4,%5,%6,%7}, {%8,%9}, {%0,%1,%2,%3};"
        : "+f"(c[0]), "+f"(c[1]), "+f"(c[2]), "+f"(c[3])
        : "r"(a0), "r"(a1), "r"(a2), "r"(a3), "r"(b0), "r"(b1));
}

// W value at (phys index p within chunk c, output col m).
// Chunks 0-3: pairwise permutation phys(2l)=k 64c+l, phys(2l+1)=64c+32+l.
// Chunk 4: identity phys p = k 256+p (valid k<300 all in steps 0-2,
//          so k-step 3 of chunk 4 is exactly zero and is skipped).
__device__ float wval(int c, int p, int m) {
    int k;
    if (c == 4) k = 256 + p;
    else        k = 64 * c + (p >> 1) + ((p & 1) ? 32 : 0);
    if (k >= DT || m >= 2 * NF) return 0.0f;
    int f = F0 + (m >> 1);
    double ang = 6.283185307179586476925286766559 * (double)f * (double)k / (double)DT;
    return (float)((m & 1) ? sin(ang) : cos(ang));
}

__global__ void build_Bfrag() {
    int t = blockIdx.x * blockDim.x + threadIdx.x;
    if (t >= NCHUNK * 4 * NTILES * 32) return;
    int lane = t & 31;
    int n = (t >> 5) % NTILES;
    int s = (t >> 5) / NTILES % 4;
    int c = t / (32 * NTILES * 4);

    int q = lane & 3, d = lane >> 2;
    int m  = 8 * n + d;
    int p0 = 16 * s + 2 * q;

    // fragment regs b0: phys rows p0, p0+1 ; b1: p0+8, p0+9 (fp16)
    __half h0 = __float2half_rn(wval(c, p0,     m));
    __half h1 = __float2half_rn(wval(c, p0 + 1, m));
    __half h2 = __float2half_rn(wval(c, p0 + 8, m));
    __half h3 = __float2half_rn(wval(c, p0 + 9, m));

    uint2 v;
    v.x = (uint32_t)__half_as_ushort(h0) | ((uint32_t)__half_as_ushort(h1) << 16);
    v.y = (uint32_t)__half_as_ushort(h2) | ((uint32_t)__half_as_ushort(h3) << 16);
    ((uint2*)g_Bfrag)[((c * 4 + s) * NTILES + n) * 32 + lane] = v;
}

// prefetch one chunk's samples for this warp's 32 rows into registers
__device__ __forceinline__ void prefetch_rows(const unsigned char* smem, int chunk,
                                              int wid, int lane,
                                              float* x1, float* x2) {
    if (chunk == 4) {
        const bool g = (lane <= 21);          // k = 256+2l(+1) <= 299
        #pragma unroll
        for (int i = 0; i < 32; ++i) {
            const int r = wid * 32 + i;
            const float* p = *(const float* const*)(smem + SM_PTR + r * 8);
            x1[i] = g ? __ldg(p + 256 + 2 * lane) : 0.0f;
            x2[i] = g ? __ldg(p + 257 + 2 * lane) : 0.0f;
        }
    } else {
        #pragma unroll
        for (int i = 0; i < 32; ++i) {
            const int r = wid * 32 + i;
            const float* p = *(const float* const*)(smem + SM_PTR + r * 8);
            x1[i] = __ldg(p + 64 * chunk + lane);        // k <= 255, valid
            x2[i] = __ldg(p + 64 * chunk + 32 + lane);   // k <= 255, valid
        }
    }
}

// split 16 rows (half=0: rows 0-15, half=1: rows 16-31) into fp16 hi/lo planes
__device__ __forceinline__ void convert_rows16(unsigned char* smem, uint32_t abuf,
                                               int wid, int lane,
                                               const float* x1, const float* x2,
                                               int half) {
    #pragma unroll
    for (int i = 0; i < 16; ++i) {
        const int idx = half * 16 + i;
        const int r = wid * 32 + idx;
        // hi = fp16(x); lo = x - hi (exactly representable in fp16)
        __half2 hp2 = __floats2half2_rn(x1[idx], x2[idx]);
        float2 hf = __half22float2(hp2);
        __half2 lp2 = __floats2half2_rn(x1[idx] - hf.x, x2[idx] - hf.y);
        const unsigned o = (unsigned)(r * ROWPITCH + lane * 4);
        *(uint32_t*)(smem + abuf + o) = *(uint32_t*)&hp2;
        *(uint32_t*)(smem + abuf + A_HALF + o) = *(uint32_t*)&lp2;
    }
}

__device__ __forceinline__ void cpasync_B(uint32_t sbase, uint32_t bbuf,
                                          int chunk, int tid) {
    const unsigned char* src = g_Bfrag + chunk * BFRAG_CHUNK;
    for (int i = tid; i < BFRAG_CHUNK / 16; i += 128) {
        asm volatile("cp.async.cg.shared.global [%0], [%1], 16;"
                     :: "r"(sbase + bbuf + i * 16), "l"(src + i * 16));
    }
    asm volatile("cp.async.commit_group;" ::: "memory");
}

// one k-step: 4 ldmatrix + 9 LDS.64 + 36 MMAs (2 m-tiles x 9 n-tiles x 2 products)
__device__ __forceinline__ void mma_step(const unsigned char* smem,
                                         uint32_t arow0, uint32_t arow1,
                                         uint32_t bbuf, int s, int lane,
                                         float* acc) {
    uint32_t ah0[4], al0[4], ah1[4], al1[4];
    ldmatrix4(ah0[0], ah0[1], ah0[2], ah0[3], arow0 + 32 * s);
    ldmatrix4(al0[0], al0[1], al0[2], al0[3], arow0 + A_HALF + 32 * s);
    ldmatrix4(ah1[0], ah1[1], ah1[2], ah1[3], arow1 + 32 * s);
    ldmatrix4(al1[0], al1[1], al1[2], al1[3], arow1 + A_HALF + 32 * s);
    #pragma unroll
    for (int n = 0; n < NTILES; ++n) {
        uint2 b = *(const uint2*)(smem + bbuf + (((s * NTILES + n) * 32 + lane) << 3));
        float* a0 = acc + n * 4;
        float* a1 = acc + (NTILES + n) * 4;
        mma16816(a0, ah0[0], ah0[1], ah0[2], ah0[3], b.x, b.y);   // Ahi * W
        mma16816(a1, ah1[0], ah1[1], ah1[2], ah1[3], b.x, b.y);
        mma16816(a0, al0[0], al0[1], al0[2], al0[3], b.x, b.y);   // Alo * W
        mma16816(a1, al1[0], al1[1], al1[2], al1[3], b.x, b.y);
    }
}

__global__ __launch_bounds__(128, 2)
void st_dft_hmma(const float* __restrict__ inp,
                 const int*   __restrict__ offs,
                 float*       __restrict__ out)
{
    extern __shared__ __align__(16) unsigned char smem[];
    const uint32_t sbase = smem_u32(smem);
    const int tid  = threadIdx.x;
    const int wid  = tid >> 5;       // 0..3, owns rows [32w, 32w+32)
    const int lane = tid & 31;
    const int base = blockIdx.x * M_TILE;

    if (tid < M_TILE) {
        int crop = base + tid;
        *(const float**)(smem + SM_PTR + tid * 8) =
            inp + (size_t)(crop >> 6) * TT + offs[crop];
    }
    __syncthreads();

    float acc[2 * NTILES * 4];
    #pragma unroll
    for (int i = 0; i < 2 * NTILES * 4; ++i) acc[i] = 0.0f;

    float x1[32], x2[32];

    // ---- prologue: stage chunk 0 (serial once) ----
    prefetch_rows(smem, 0, wid, lane, x1, x2);
    cpasync_B(sbase, SM_B0, 0, tid);
    convert_rows16(smem, SM_A0, wid, lane, x1, x2, 0);
    convert_rows16(smem, SM_A0, wid, lane, x1, x2, 1);
    asm volatile("cp.async.wait_group 0;" ::: "memory");
    __syncthreads();

    const uint32_t lane_a = (uint32_t)((32 * wid + (lane & 15)) * ROWPITCH
                                       + ((lane >> 4) << 4));

    // ---- chunks 0..3: 4 k-steps, convert(c+1) interleaved at s=2,3 ----
    #pragma unroll 1
    for (int c = 0; c < NCHUNK - 1; ++c) {
        const uint32_t abuf = (c & 1) ? SM_A1 : SM_A0;
        const uint32_t bbuf = (c & 1) ? SM_B1 : SM_B0;
        const uint32_t nabuf = (c & 1) ? SM_A0 : SM_A1;
        const uint32_t nbbuf = (c & 1) ? SM_B0 : SM_B1;

        // issue next chunk's loads; ~2 MMA steps of latency cover before use
        prefetch_rows(smem, c + 1, wid, lane, x1, x2);
        cpasync_B(sbase, nbbuf, c + 1, tid);

        const uint32_t arow0 = sbase + abuf + lane_a;
        const uint32_t arow1 = arow0 + 16 * ROWPITCH;

        mma_step(smem, arow0, arow1, bbuf, 0, lane, acc);
        mma_step(smem, arow0, arow1, bbuf, 1, lane, acc);
        mma_step(smem, arow0, arow1, bbuf, 2, lane, acc);
        convert_rows16(smem, nabuf, wid, lane, x1, x2, 0);   // interleaves w/ s=2
        mma_step(smem, arow0, arow1, bbuf, 3, lane, acc);
        convert_rows16(smem, nabuf, wid, lane, x1, x2, 1);   // interleaves w/ s=3

        asm volatile("cp.async.wait_group 0;" ::: "memory");
        __syncthreads();
    }

    // ---- chunk 4: only 3 k-steps carry data (identity permutation) ----
    {
        const uint32_t arow0 = sbase + SM_A0 + lane_a;       // chunk 4 -> buf 0
        const uint32_t arow1 = arow0 + 16 * ROWPITCH;
        mma_step(smem, arow0, arow1, SM_B0, 0, lane, acc);
        mma_step(smem, arow0, arow1, SM_B0, 1, lane, acc);
        mma_step(smem, arow0, arow1, SM_B0, 2, lane, acc);
    }
    __syncthreads();   // all mma reads done before reusing A buffer for staging

    // --- epilogue: power, band-normalize, stage, coalesced store ---
    {
        const int q = lane & 3;
        float* pw = (float*)(smem + SM_POW);

        #pragma unroll
        for (int t = 0; t < 2; ++t) {
            const int rA = 32 * wid + 16 * t + (lane >> 2);
            const int rB = rA + 8;
            const float* a = acc + t * NTILES * 4;

            float pA[NTILES], pB[NTILES];
            float sA = 0.0f, sB = 0.0f;
            #pragma unroll
            for (int n = 0; n < NTILES; ++n) {
                pA[n] = fmaf(a[n*4+0], a[n*4+0], a[n*4+1] * a[n*4+1]);
                pB[n] = fmaf(a[n*4+2], a[n*4+2], a[n*4+3] * a[n*4+3]);
                sA += pA[n];  sB += pB[n];   // pad col j=35 contributes 0
            }
            sA += __shfl_xor_sync(0xffffffffu, sA, 1);
            sA += __shfl_xor_sync(0xffffffffu, sA, 2);
            sB += __shfl_xor_sync(0xffffffffu, sB, 1);
            sB += __shfl_xor_sync(0xffffffffu, sB, 2);
            const float iA = 1.0f / sA, iB = 1.0f / sB;

            #pragma unroll
            for (int n = 0; n < NTILES; ++n) {
                int j = 4 * n + q;
                if (j < NF) {
                    pw[rA * NF + j] = pA[n] * iA;
                    pw[rB * NF + j] = pB[n] * iB;
                }
            }
        }
    }
    __syncthreads();

    {
        uint4* o = (uint4*)(out + (size_t)base * NF);
        const uint4* s = (const uint4*)(smem + SM_POW);
        #pragma unroll 2
        for (int i = tid; i < (M_TILE * NF * 4) / 16; i += 128) o[i] = s[i];
    }
}

extern "C" void kernel_launch(void* const* d_in, const int* in_sizes, int n_in,
                              void* d_out, int out_size)
{
    const float* inp  = (const float*)d_in[0];   // [B, C, T] float32
    const int*   offs = (const int*)  d_in[1];   // [B, C, K] int32
    float*       out  = (float*)d_out;           // [B, C, K, NF] float32

    (void)in_sizes; (void)n_in; (void)out_size;

    static int configured = 0;
    if (!configured) {
        cudaFuncSetAttribute(st_dft_hmma,
                             cudaFuncAttributeMaxDynamicSharedMemorySize, SM_TOTAL);
        configured = 1;
    }

    build_Bfrag<<<(NCHUNK * 4 * NTILES * 32 + 255) / 256, 256>>>();
    st_dft_hmma<<<NCROP / M_TILE, 128, SM_TOTAL>>>(inp, offs, out);
}

// round 17
// speedup vs baseline: 4.6392x; 1.4961x over previous
#include <cuda_runtime.h>
#include <cuda_fp16.h>
#include <math.h>
#include <stdint.h>

// ---------------- problem constants ----------------
#define BB 256
#define CC 16
#define TT 9000
#define KK 64
#define DT 300
#define F0 7
#define NF 35
#define NCROP (BB*CC*KK)      // 262144

// ---------------- tile constants ----------------
#define M_TILE   128          // crops per CTA (4 warps x 32 rows)
#define NTILES   9            // 72 cols / 8
#define NCHUNK   5            // K = 5 * 64 (logical 300, rest zero)
#define ROWPITCH 144          // bytes per A row in SMEM (64 fp16 + 16 pad)
#define A_PLANE  (M_TILE*ROWPITCH)       // 18432 (single fp16 plane)

// B fragments: [chunk][kstep 4][ntile 9][lane 32] x uint2{b0,b1} (fp16)
#define BFRAG_CHUNK (4*NTILES*32*8)      // 9216 B
#define BFRAG_BYTES (NCHUNK*BFRAG_CHUNK) // 46080 B

// ---------------- dynamic SMEM layout ----------------
#define SM_PTR  0                        // 128 crop pointers (8 B each)
#define SM_A0   1024
#define SM_A1   (SM_A0 + A_PLANE)        // 19456
#define SM_B0   (SM_A1 + A_PLANE)        // 37888
#define SM_B1   (SM_B0 + BFRAG_CHUNK)    // 47104
#define SM_POW  SM_A0                    // epilogue staging (17920 B)
#define SM_TOTAL (SM_B1 + BFRAG_CHUNK)   // 56320  -> 3 CTAs/SM

__device__ __align__(16) unsigned char g_Bfrag[BFRAG_BYTES];

// ---------------- helpers ----------------
__device__ __forceinline__ uint32_t smem_u32(const void* p) {
    uint32_t a;
    asm("{ .reg .u64 t; cvta.to.shared.u64 t, %1; cvt.u32.u64 %0, t; }"
        : "=r"(a) : "l"(p));
    return a;
}
__device__ __forceinline__ void ldmatrix4(uint32_t& r0, uint32_t& r1,
                                          uint32_t& r2, uint32_t& r3,
                                          uint32_t addr) {
    asm volatile("ldmatrix.sync.aligned.m8n8.x4.shared.b16 {%0,%1,%2,%3}, [%4];"
                 : "=r"(r0), "=r"(r1), "=r"(r2), "=r"(r3) : "r"(addr));
}
__device__ __forceinline__ void mma16816(float* c, uint32_t a0, uint32_t a1,
                                         uint32_t a2, uint32_t a3,
                                         uint32_t b0, uint32_t b1) {
    asm volatile(
        "mma.sync.aligned.m16n8k16.row.col.f32.f16.f16.f32 "
        "{%0,%1,%2,%3}, {%4,%5,%6,%7}, {%8,%9}, {%0,%1,%2,%3};"
        : "+f"(c[0]), "+f"(c[1]), "+f"(c[2]), "+f"(c[3])
        : "r"(a0), "r"(a1), "r"(a2), "r"(a3), "r"(b0), "r"(b1));
}

// W value at (phys index p within chunk c, output col m).
// Chunks 0-3: pairwise permutation phys(2l)=k 64c+l, phys(2l+1)=64c+32+l.
// Chunk 4: identity phys p = k 256+p (valid k<300 all in steps 0-2,
//          so k-step 3 of chunk 4 is exactly zero and is skipped).
__device__ float wval(int c, int p, int m) {
    int k;
    if (c == 4) k = 256 + p;
    else        k = 64 * c + (p >> 1) + ((p & 1) ? 32 : 0);
    if (k >= DT || m >= 2 * NF) return 0.0f;
    int f = F0 + (m >> 1);
    float ang = 6.2831853071795864769f * (float)f * (float)k / (float)DT;
    float s, cc2;
    __sincosf(ang, &s, &cc2);            // fast path; fp16 rounding dominates
    // use precise single-precision versions (still cheap, better than __sincosf)
    s  = sinf(ang);
    cc2 = cosf(ang);
    return (m & 1) ? s : cc2;
}

__global__ void build_Bfrag() {
    int t = blockIdx.x * blockDim.x + threadIdx.x;
    if (t >= NCHUNK * 4 * NTILES * 32) return;
    int lane = t & 31;
    int n = (t >> 5) % NTILES;
    int s = (t >> 5) / NTILES % 4;
    int c = t / (32 * NTILES * 4);

    int q = lane & 3, d = lane >> 2;
    int m  = 8 * n + d;
    int p0 = 16 * s + 2 * q;

    // fragment regs b0: phys rows p0, p0+1 ; b1: p0+8, p0+9 (fp16)
    __half h0 = __float2half_rn(wval(c, p0,     m));
    __half h1 = __float2half_rn(wval(c, p0 + 1, m));
    __half h2 = __float2half_rn(wval(c, p0 + 8, m));
    __half h3 = __float2half_rn(wval(c, p0 + 9, m));

    uint2 v;
    v.x = (uint32_t)__half_as_ushort(h0) | ((uint32_t)__half_as_ushort(h1) << 16);
    v.y = (uint32_t)__half_as_ushort(h2) | ((uint32_t)__half_as_ushort(h3) << 16);
    ((uint2*)g_Bfrag)[((c * 4 + s) * NTILES + n) * 32 + lane] = v;
}

// prefetch one chunk's samples for this warp's 32 rows into registers
__device__ __forceinline__ void prefetch_rows(const unsigned char* smem, int chunk,
                                              int wid, int lane,
                                              float* x1, float* x2) {
    if (chunk == 4) {
        const bool g = (lane <= 21);          // k = 256+2l(+1) <= 299
        #pragma unroll
        for (int i = 0; i < 32; ++i) {
            const int r = wid * 32 + i;
            const float* p = *(const float* const*)(smem + SM_PTR + r * 8);
            x1[i] = g ? __ldg(p + 256 + 2 * lane) : 0.0f;
            x2[i] = g ? __ldg(p + 257 + 2 * lane) : 0.0f;
        }
    } else {
        #pragma unroll
        for (int i = 0; i < 32; ++i) {
            const int r = wid * 32 + i;
            const float* p = *(const float* const*)(smem + SM_PTR + r * 8);
            x1[i] = __ldg(p + 64 * chunk + lane);        // k <= 255, valid
            x2[i] = __ldg(p + 64 * chunk + 32 + lane);   // k <= 255, valid
        }
    }
}

// convert 16 rows (half=0: rows 0-15, half=1: rows 16-31) to fp16 plane
__device__ __forceinline__ void convert_rows16(unsigned char* smem, uint32_t abuf,
                                               int wid, int lane,
                                               const float* x1, const float* x2,
                                               int half) {
    #pragma unroll
    for (int i = 0; i < 16; ++i) {
        const int idx = half * 16 + i;
        const int r = wid * 32 + idx;
        __half2 hp2 = __floats2half2_rn(x1[idx], x2[idx]);
        const unsigned o = (unsigned)(r * ROWPITCH + lane * 4);
        *(uint32_t*)(smem + abuf + o) = *(uint32_t*)&hp2;
    }
}

__device__ __forceinline__ void cpasync_B(uint32_t sbase, uint32_t bbuf,
                                          int chunk, int tid) {
    const unsigned char* src = g_Bfrag + chunk * BFRAG_CHUNK;
    for (int i = tid; i < BFRAG_CHUNK / 16; i += 128) {
        asm volatile("cp.async.cg.shared.global [%0], [%1], 16;"
                     :: "r"(sbase + bbuf + i * 16), "l"(src + i * 16));
    }
    asm volatile("cp.async.commit_group;" ::: "memory");
}

// one k-step: 2 ldmatrix + 9 LDS.64 + 18 MMAs (2 m-tiles x 9 n-tiles)
__device__ __forceinline__ void mma_step(const unsigned char* smem,
                                         uint32_t arow0, uint32_t arow1,
                                         uint32_t bbuf, int s, int lane,
                                         float* acc) {
    uint32_t a0[4], a1[4];
    ldmatrix4(a0[0], a0[1], a0[2], a0[3], arow0 + 32 * s);
    ldmatrix4(a1[0], a1[1], a1[2], a1[3], arow1 + 32 * s);
    #pragma unroll
    for (int n = 0; n < NTILES; ++n) {
        uint2 b = *(const uint2*)(smem + bbuf + (((s * NTILES + n) * 32 + lane) << 3));
        mma16816(acc + n * 4,            a0[0], a0[1], a0[2], a0[3], b.x, b.y);
        mma16816(acc + (NTILES + n) * 4, a1[0], a1[1], a1[2], a1[3], b.x, b.y);
    }
}

__global__ __launch_bounds__(128, 3)
void st_dft_hmma(const float* __restrict__ inp,
                 const int*   __restrict__ offs,
                 float*       __restrict__ out)
{
    extern __shared__ __align__(16) unsigned char smem[];
    const uint32_t sbase = smem_u32(smem);
    const int tid  = threadIdx.x;
    const int wid  = tid >> 5;       // 0..3, owns rows [32w, 32w+32)
    const int lane = tid & 31;
    const int base = blockIdx.x * M_TILE;

    if (tid < M_TILE) {
        int crop = base + tid;
        *(const float**)(smem + SM_PTR + tid * 8) =
            inp + (size_t)(crop >> 6) * TT + offs[crop];
    }
    __syncthreads();

    float acc[2 * NTILES * 4];
    #pragma unroll
    for (int i = 0; i < 2 * NTILES * 4; ++i) acc[i] = 0.0f;

    float x1[32], x2[32];

    // ---- prologue: stage chunk 0 (serial once) ----
    prefetch_rows(smem, 0, wid, lane, x1, x2);
    cpasync_B(sbase, SM_B0, 0, tid);
    convert_rows16(smem, SM_A0, wid, lane, x1, x2, 0);
    convert_rows16(smem, SM_A0, wid, lane, x1, x2, 1);
    asm volatile("cp.async.wait_group 0;" ::: "memory");
    __syncthreads();

    const uint32_t lane_a = (uint32_t)((32 * wid + (lane & 15)) * ROWPITCH
                                       + ((lane >> 4) << 4));

    // ---- chunks 0..3: 4 k-steps, convert(c+1) interleaved at s=2,3 ----
    #pragma unroll 1
    for (int c = 0; c < NCHUNK - 1; ++c) {
        const uint32_t abuf = (c & 1) ? SM_A1 : SM_A0;
        const uint32_t bbuf = (c & 1) ? SM_B1 : SM_B0;
        const uint32_t nabuf = (c & 1) ? SM_A0 : SM_A1;
        const uint32_t nbbuf = (c & 1) ? SM_B0 : SM_B1;

        // issue next chunk's loads; ~2 MMA steps of latency cover before use
        prefetch_rows(smem, c + 1, wid, lane, x1, x2);
        cpasync_B(sbase, nbbuf, c + 1, tid);

        const uint32_t arow0 = sbase + abuf + lane_a;
        const uint32_t arow1 = arow0 + 16 * ROWPITCH;

        mma_step(smem, arow0, arow1, bbuf, 0, lane, acc);
        mma_step(smem, arow0, arow1, bbuf, 1, lane, acc);
        mma_step(smem, arow0, arow1, bbuf, 2, lane, acc);
        convert_rows16(smem, nabuf, wid, lane, x1, x2, 0);   // interleaves w/ s=2
        mma_step(smem, arow0, arow1, bbuf, 3, lane, acc);
        convert_rows16(smem, nabuf, wid, lane, x1, x2, 1);   // interleaves w/ s=3

        asm volatile("cp.async.wait_group 0;" ::: "memory");
        __syncthreads();
    }

    // ---- chunk 4: only 3 k-steps carry data (identity permutation) ----
    {
        const uint32_t arow0 = sbase + SM_A0 + lane_a;       // chunk 4 -> buf 0
        const uint32_t arow1 = arow0 + 16 * ROWPITCH;
        mma_step(smem, arow0, arow1, SM_B0, 0, lane, acc);
        mma_step(smem, arow0, arow1, SM_B0, 1, lane, acc);
        mma_step(smem, arow0, arow1, SM_B0, 2, lane, acc);
    }
    __syncthreads();   // all mma reads done before reusing A buffer for staging

    // --- epilogue: power, band-normalize, stage, coalesced store ---
    {
        const int q = lane & 3;
        float* pw = (float*)(smem + SM_POW);

        #pragma unroll
        for (int t = 0; t < 2; ++t) {
            const int rA = 32 * wid + 16 * t + (lane >> 2);
            const int rB = rA + 8;
            const float* a = acc + t * NTILES * 4;

            float pA[NTILES], pB[NTILES];
            float sA = 0.0f, sB = 0.0f;
            #pragma unroll
            for (int n = 0; n < NTILES; ++n) {
                pA[n] = fmaf(a[n*4+0], a[n*4+0], a[n*4+1] * a[n*4+1]);
                pB[n] = fmaf(a[n*4+2], a[n*4+2], a[n*4+3] * a[n*4+3]);
                sA += pA[n];  sB += pB[n];   // pad col j=35 contributes 0
            }
            sA += __shfl_xor_sync(0xffffffffu, sA, 1);
            sA += __shfl_xor_sync(0xffffffffu, sA, 2);
            sB += __shfl_xor_sync(0xffffffffu, sB, 1);
            sB += __shfl_xor_sync(0xffffffffu, sB, 2);
            const float iA = 1.0f / sA, iB = 1.0f / sB;

            #pragma unroll
            for (int n = 0; n < NTILES; ++n) {
                int j = 4 * n + q;
                if (j < NF) {
                    pw[rA * NF + j] = pA[n] * iA;
                    pw[rB * NF + j] = pB[n] * iB;
                }
            }
        }
    }
    __syncthreads();

    {
        uint4* o = (uint4*)(out + (size_t)base * NF);
        const uint4* s = (const uint4*)(smem + SM_POW);
        #pragma unroll 2
        for (int i = tid; i < (M_TILE * NF * 4) / 16; i += 128) o[i] = s[i];
    }
}

extern "C" void kernel_launch(void* const* d_in, const int* in_sizes, int n_in,
                              void* d_out, int out_size)
{
    const float* inp  = (const float*)d_in[0];   // [B, C, T] float32
    const int*   offs = (const int*)  d_in[1];   // [B, C, K] int32
    float*       out  = (float*)d_out;           // [B, C, K, NF] float32

    (void)in_sizes; (void)n_in; (void)out_size;

    static int configured = 0;
    if (!configured) {
        cudaFuncSetAttribute(st_dft_hmma,
                             cudaFuncAttributeMaxDynamicSharedMemorySize, SM_TOTAL);
        configured = 1;
    }

    build_Bfrag<<<(NCHUNK * 4 * NTILES * 32 + 255) / 256, 256>>>();
    st_dft_hmma<<<NCROP / M_TILE, 128, SM_TOTAL>>>(inp, offs, out);
}